// round 11
// baseline (speedup 1.0000x reference)
#include <cuda_runtime.h>
#include <cuda_bf16.h>

// PointPWC loss, B=1, N=8192.
// total = 0.02*chamfer + 0.006*curv + 0.01*smooth
//
// R10: x-sorted pruned kNN (kills the O(N^2) scan).
//  - bucket counting-sort (1024 x-buckets) of pc1/pc2/warp clouds
//  - per-query two-frontier outward scan, batched x8, side pruned when
//    (|dx| - bucketW)^2 > kth_true  (bucket slack => exact under within-bucket
//    disorder; scan covers all indices, so completeness is structural)
//  - quasi-nearest-first order => insert events (dominant cost in the brute
//    force versions) collapse along with candidate count (~1100 vs 8192)
//  - epilogues fused inline (R9 pattern); queries iterate in sorted order so
//    warp lanes share slabs (L1 hits, correlated loop extents)

#define MAXN  8192
#define KNN   10
#define KNN5  5
#define TPB   128
#define NB    1024
#define XMIN  (-8.0f)
#define BSCALE 64.0f           // NB / 16
#define BW    0.015625f        // 16 / NB

__device__ float4 g_pc1[MAXN], g_pc2[MAXN], g_warp[MAXN], g_flow[MAXN];
__device__ float4 g_p1s[MAXN], g_p2s[MAXN], g_ws[MAXN];   // x-bucket-sorted
__device__ float4 g_flow1s[MAXN], g_warp1s[MAXN];         // in pc1-sorted order
__device__ int    g_idx1[MAXN];                            // pc1-sorted -> orig
__device__ int    g_idxw[MAXN];                            // warp-sorted -> orig
__device__ float4 g_c2s[MAXN];    // curvature of pc2 (pc2-sorted order)
__device__ float4 g_moved[MAXN];  // moved curvature (orig order)
__device__ float  g_pd5[MAXN * KNN5];   // orig-order i-major
__device__ int    g_pi5[MAXN * KNN5];   // indices in pc2-sorted space
__device__ int    g_bins[3 * NB];
__device__ double g_acc[4];  // 0: chamfer fwd, 1: chamfer bwd, 2: smooth, 3: curv

__device__ __forceinline__ int bucketf(float x) {
    int b = (int)((x - XMIN) * BSCALE);
    return min(max(b, 0), NB - 1);
}

__device__ __forceinline__ double warp_red(double v) {
    #pragma unroll
    for (int o = 16; o > 0; o >>= 1)
        v += __shfl_down_sync(0xffffffffu, v, o);
    return v;
}

__global__ void zero_kernel() {
    int gid = blockIdx.x * blockDim.x + threadIdx.x;
    if (gid < 3 * NB) g_bins[gid] = 0;
    if (gid < 4) g_acc[gid] = 0.0;
}

__global__ void prep_kernel(const float* __restrict__ pred,
                            const float* __restrict__ gt,
                            const float* __restrict__ coords, int n) {
    int i = blockIdx.x * blockDim.x + threadIdx.x;
    if (i >= n) return;
    float cx = coords[3 * i + 0], cy = coords[3 * i + 1], cz = coords[3 * i + 2];
    float gx = gt[3 * i + 0],     gy = gt[3 * i + 1],     gz = gt[3 * i + 2];
    float fx = pred[3 * i + 0],   fy = pred[3 * i + 1],   fz = pred[3 * i + 2];
    float p2x = cx + gx, p2y = cy + gy, p2z = cz + gz;
    float wx  = cx + fx, wy  = cy + fy, wz  = cz + fz;
    g_pc1[i]  = make_float4(cx, cy, cz, cx * cx + cy * cy + cz * cz);
    g_pc2[i]  = make_float4(p2x, p2y, p2z, p2x * p2x + p2y * p2y + p2z * p2z);
    g_warp[i] = make_float4(wx, wy, wz, wx * wx + wy * wy + wz * wz);
    g_flow[i] = make_float4(fx, fy, fz, 0.f);
    atomicAdd(&g_bins[bucketf(cx)], 1);
    atomicAdd(&g_bins[NB + bucketf(p2x)], 1);
    atomicAdd(&g_bins[2 * NB + bucketf(wx)], 1);
}

// exclusive prefix over each of the 3 histograms; one block of NB threads
__global__ void scan_kernel() {
    __shared__ int s[NB];
    int t = threadIdx.x;
    for (int h = 0; h < 3; h++) {
        int orig = g_bins[h * NB + t];
        s[t] = orig;
        __syncthreads();
        for (int o = 1; o < NB; o <<= 1) {
            int v = (t >= o) ? s[t - o] : 0;
            __syncthreads();
            s[t] += v;
            __syncthreads();
        }
        g_bins[h * NB + t] = s[t] - orig;  // exclusive
        __syncthreads();
    }
}

__global__ void scatter_kernel(int n) {
    int i = blockIdx.x * blockDim.x + threadIdx.x;
    if (i >= n) return;
    float4 p1 = g_pc1[i];
    int s1 = atomicAdd(&g_bins[bucketf(p1.x)], 1);
    g_p1s[s1] = p1;
    g_flow1s[s1] = g_flow[i];
    g_warp1s[s1] = g_warp[i];
    g_idx1[s1] = i;
    float4 p2 = g_pc2[i];
    int s2 = atomicAdd(&g_bins[NB + bucketf(p2.x)], 1);
    g_p2s[s2] = p2;
    float4 w = g_warp[i];
    int sw = atomicAdd(&g_bins[2 * NB + bucketf(w.x)], 1);
    g_ws[sw] = w;
    g_idxw[sw] = i;
}

template <int K>
__device__ __forceinline__ void insert_sorted(float dm, int j,
                                              float (&d)[K], int (&id)[K],
                                              float& kth) {
    d[K - 1] = dm; id[K - 1] = j;
    #pragma unroll
    for (int s = K - 1; s > 0; --s) {
        if (d[s] < d[s - 1]) {
            float td = d[s]; d[s] = d[s - 1]; d[s - 1] = td;
            int   ti = id[s]; id[s] = id[s - 1]; id[s - 1] = ti;
        }
    }
    kth = d[K - 1];
}

// Two-frontier pruned scan over x-bucket-sorted S. dm = |p|^2 - 2<q,p>;
// true dist^2 = dm + q.w. Prune a side when even the slack-adjusted x-gap
// exceeds kth_true. Strict '<' keeps first-seen on exact ties (only self,
// which is strictly minimal, so selection == lax.top_k for this data).
template <int K>
__device__ __forceinline__ void nnscan(const float4* __restrict__ S, int n,
                                       float4 q, int pos,
                                       float (&d)[K], int (&id)[K]) {
    #pragma unroll
    for (int t = 0; t < K; t++) { d[t] = 3.4e38f; id[t] = 0; }
    float kth = 3.4e38f;
    int lo = pos - 1, hi = pos;
    bool loA = (lo >= 0), hiA = (hi < n);
    while (loA || hiA) {
        if (loA) {
            float xl = 0.f;
            #pragma unroll
            for (int b = 0; b < 8; b++) {
                int j = lo - b;
                int jc = j < 0 ? 0 : j;
                float4 p = S[jc];
                float dot = fmaf(q.x, p.x, fmaf(q.y, p.y, q.z * p.z));
                float dm  = fmaf(-2.f, dot, p.w);
                if (j < 0) dm = 3.4e38f;
                if (dm < kth) insert_sorted<K>(dm, jc, d, id, kth);
                if (b == 7) xl = p.x;
            }
            lo -= 8;
            float kt = kth + q.w;
            float dxm = q.x - xl - BW;
            loA = (lo >= 0) && !(dxm > 0.f && dxm * dxm > kt);
        }
        if (hiA) {
            float xh = 0.f;
            #pragma unroll
            for (int b = 0; b < 8; b++) {
                int j = hi + b;
                int jc = j >= n ? n - 1 : j;
                float4 p = S[jc];
                float dot = fmaf(q.x, p.x, fmaf(q.y, p.y, q.z * p.z));
                float dm  = fmaf(-2.f, dot, p.w);
                if (j >= n) dm = 3.4e38f;
                if (dm < kth) insert_sorted<K>(dm, jc, d, id, kth);
                if (b == 7) xh = p.x;
            }
            hi += 8;
            float kt = kth + q.w;
            float dxm = xh - q.x - BW;
            hiA = (hi < n) && !(dxm > 0.f && dxm * dxm > kt);
        }
    }
}

// min-only variant (reverse chamfer)
__device__ __forceinline__ float nnmin(const float4* __restrict__ S, int n,
                                       float4 q, int pos) {
    float m = 3.4e38f;
    int lo = pos - 1, hi = pos;
    bool loA = (lo >= 0), hiA = (hi < n);
    while (loA || hiA) {
        if (loA) {
            float xl = 0.f;
            #pragma unroll
            for (int b = 0; b < 8; b++) {
                int j = lo - b;
                int jc = j < 0 ? 0 : j;
                float4 p = S[jc];
                float dot = fmaf(q.x, p.x, fmaf(q.y, p.y, q.z * p.z));
                float dm  = fmaf(-2.f, dot, p.w);
                if (j >= 0) m = fminf(m, dm);
                if (b == 7) xl = p.x;
            }
            lo -= 8;
            float kt = m + q.w;
            float dxm = q.x - xl - BW;
            loA = (lo >= 0) && !(dxm > 0.f && dxm * dxm > kt);
        }
        if (hiA) {
            float xh = 0.f;
            #pragma unroll
            for (int b = 0; b < 8; b++) {
                int j = hi + b;
                int jc = j >= n ? n - 1 : j;
                float4 p = S[jc];
                float dot = fmaf(q.x, p.x, fmaf(q.y, p.y, q.z * p.z));
                float dm  = fmaf(-2.f, dot, p.w);
                if (j < n) m = fminf(m, dm);
                if (b == 7) xh = p.x;
            }
            hi += 8;
            float kt = m + q.w;
            float dxm = xh - q.x - BW;
            hiA = (hi < n) && !(dxm > 0.f && dxm * dxm > kt);
        }
    }
    return m;
}

__device__ __forceinline__ int lbound(const float4* __restrict__ S, int n, float x) {
    int lo = 0, hi = n;
    while (lo < hi) {
        int mid = (lo + hi) >> 1;
        if (S[mid].x < x) lo = mid + 1; else hi = mid;
    }
    return lo;
}

// grid = (n/TPB, 1, 4); epilogues fused.
__global__ void __launch_bounds__(TPB) pairs_kernel(int n, const int* __restrict__ kptr) {
    const int slice = blockIdx.z;
    const int i = blockIdx.x * TPB + threadIdx.x;
    const int ii = (i < n) ? i : 0;

    if (slice == 0) {
        // pc2 self-knn -> curvature of pc2 (pc2-sorted order)
        float4 q = g_p2s[ii];
        float d[KNN]; int id[KNN];
        nnscan<KNN>(g_p2s, n, q, ii, d, id);
        if (i < n) {
            float sx = 0.f, sy = 0.f, sz = 0.f;
            #pragma unroll
            for (int t = 0; t < KNN; t++) {
                float4 p = g_p2s[id[t]];
                sx += p.x; sy += p.y; sz += p.z;
            }
            g_c2s[i] = make_float4((sx - 10.f * q.x) / 9.f,
                                   (sy - 10.f * q.y) / 9.f,
                                   (sz - 10.f * q.z) / 9.f, 0.f);
        }
    } else if (slice == 1) {
        // pc1 self-knn -> moved curvature (scatter to orig) + smoothness
        float4 q = g_p1s[ii];
        float d[KNN]; int id[KNN];
        nnscan<KNN>(g_p1s, n, q, ii, d, id);
        double sm_d = 0.0;
        if (i < n) {
            float4 w = g_warp1s[i];
            float sx = 0.f, sy = 0.f, sz = 0.f;
            #pragma unroll
            for (int t = 0; t < KNN; t++) {
                float4 p = g_warp1s[id[t]];
                sx += p.x; sy += p.y; sz += p.z;
            }
            g_moved[g_idx1[i]] = make_float4((sx - 10.f * w.x) / 9.f,
                                             (sy - 10.f * w.y) / 9.f,
                                             (sz - 10.f * w.z) / 9.f, 0.f);
            int k = *kptr;
            float4 f = g_flow1s[i];
            float sm = 0.f;
            #pragma unroll
            for (int t = 0; t < KNN; t++) {
                if (t < k) {
                    float4 gfl = g_flow1s[id[t]];
                    float dx = gfl.x - f.x, dy = gfl.y - f.y, dz = gfl.z - f.z;
                    float sq = dx * dx + dy * dy + dz * dz;
                    sm += sqrtf(sq);   // sq==0 (self) -> 0, matches safe-norm
                }
            }
            sm_d = (double)(sm / 8.f);
        }
        double v = warp_red(sm_d);
        if ((threadIdx.x & 31) == 0) atomicAdd(&g_acc[2], v);
    } else if (slice == 2) {
        // warp -> pc2 top-5 (warp-sorted query order): chamfer fwd + store
        float4 q = g_ws[ii];
        int pos = lbound(g_p2s, n, q.x);
        float d[KNN5]; int id[KNN5];
        nnscan<KNN5>(g_p2s, n, q, pos, d, id);
        double d1 = 0.0;
        if (i < n) {
            d1 = (double)(d[0] + q.w);
            int orig = g_idxw[i];
            #pragma unroll
            for (int t = 0; t < KNN5; t++) {
                g_pd5[orig * KNN5 + t] = d[t] + q.w;
                g_pi5[orig * KNN5 + t] = id[t];
            }
        }
        double v = warp_red(d1);
        if ((threadIdx.x & 31) == 0) atomicAdd(&g_acc[0], v);
    } else {
        // pc2 -> warp min (reverse chamfer)
        float4 q = g_p2s[ii];
        int pos = lbound(g_ws, n, q.x);
        float m = nnmin(g_ws, n, q, pos);
        double v = (i < n) ? (double)(m + q.w) : 0.0;
        double s = warp_red(v);
        if ((threadIdx.x & 31) == 0) atomicAdd(&g_acc[1], s);
    }
}

// Interp-curvature loss (needs c2s + moved from pairs).
__global__ void cross_consume_kernel(int n) {
    int i = blockIdx.x * blockDim.x + threadIdx.x;
    double cv = 0.0;
    if (i < n) {
        float w[KNN5]; float wsum = 0.f;
        int id[KNN5];
        #pragma unroll
        for (int t = 0; t < KNN5; t++) {
            float dist = g_pd5[i * KNN5 + t];
            id[t] = g_pi5[i * KNN5 + t];
            w[t] = 1.f / (dist + 1e-8f);
            wsum += w[t];
        }
        float ix = 0.f, iy = 0.f, iz = 0.f;
        #pragma unroll
        for (int t = 0; t < KNN5; t++) {
            float wn = w[t] / wsum;
            float4 c = g_c2s[id[t]];
            ix = fmaf(wn, c.x, ix);
            iy = fmaf(wn, c.y, iy);
            iz = fmaf(wn, c.z, iz);
        }
        float4 m = g_moved[i];
        float ex = ix - m.x, ey = iy - m.y, ez = iz - m.z;
        cv = (double)(ex * ex + ey * ey + ez * ez);
    }
    double v1 = warp_red(cv);
    if ((threadIdx.x & 31) == 0) atomicAdd(&g_acc[3], v1);
}

__global__ void finalize_kernel(float* __restrict__ out) {
    if (threadIdx.x == 0) {
        double chamfer = g_acc[0] + g_acc[1];
        double total = 0.02 * chamfer      // F_CHAMFER * ALPHA0
                     + 0.006 * g_acc[3]    // F_CURVATURE * ALPHA0
                     + 0.01  * g_acc[2];   // F_SMOOTH * ALPHA0
        out[0] = (float)total;
    }
}

extern "C" void kernel_launch(void* const* d_in, const int* in_sizes, int n_in,
                              void* d_out, int out_size) {
    const float* pred   = (const float*)d_in[0];  // registration_pred (1,N,3)
    const float* gt     = (const float*)d_in[1];  // registration_gt   (1,N,3)
    const float* coords = (const float*)d_in[2];  // coords            (N,3)
    const int*   kptr   = (const int*)d_in[3];    // smoothness_k

    int n = in_sizes[2] / 3;   // 8192
    int cb = (n + 255) / 256;

    zero_kernel<<<3, 1024>>>();
    prep_kernel<<<cb, 256>>>(pred, gt, coords, n);
    scan_kernel<<<1, NB>>>();
    scatter_kernel<<<cb, 256>>>(n);
    pairs_kernel<<<dim3(n / TPB, 1, 4), TPB>>>(n, kptr);
    cross_consume_kernel<<<cb, 256>>>(n);
    finalize_kernel<<<1, 32>>>((float*)d_out);
}

// round 13
// speedup vs baseline: 1.7626x; 1.7626x over previous
#include <cuda_runtime.h>
#include <cuda_bf16.h>

// PointPWC loss, B=1, N=8192.
// total = 0.02*chamfer + 0.006*curv + 0.01*smooth
//
// R11: sorted-window scan inside the R7 high-occupancy skeleton.
//  - x-bucket counting sort of pc1/pc2/warp (bucket granularity BW; pruning
//    bounds carry BW slack, so within-bucket disorder is safe).
//  - pairs: grid (32, 2, 4) @ TPB=256 (2048 warps, R7 occupancy). Block b
//    owns 256 x-sorted queries; chunk 0 scans smem tiles leftward from a
//    shared split 'mid', chunk 1 rightward. After each tile a block-uniform
//    __syncthreads_and vote stops the walk when the frontier x-gap (minus BW)
//    squared exceeds every lane's kth true distance. Positional coverage
//    [0,mid) U [mid,n) + per-side prune bound => exact top-K.
//  - near-to-far scan order collapses the sorted-insert transient (the
//    dominant cost in all brute-force rounds).
//  - sentinel pads (x=+-1e18, w=3.4e38) on both ends: never insertable,
//    force the vote to pass at array boundaries.
//  - partials: R7's proven i-major 2-chunk scratch + merge consumes.

#define MAXN  8192
#define KNN   10
#define KNN5  5
#define TPB   256
#define PAD   256
#define PADN  (MAXN + 2 * PAD)
#define NB    1024
#define XMIN  (-8.0f)
#define BSCALE 64.0f           // NB / 16
#define BW    0.015625f        // 16 / NB

__device__ float4 g_pc1[MAXN], g_pc2[MAXN], g_warp[MAXN], g_flow[MAXN];
__device__ float4 g_p1s[PADN], g_p2s[PADN], g_ws[PADN];     // sorted + pads
__device__ float4 g_flow1s[PADN], g_warp1s[PADN];           // pc1-sorted order (padded addressing)
__device__ int    g_idx1[MAXN];   // pc1-sorted -> orig
__device__ int    g_idxw[MAXN];   // warp-sorted -> orig
__device__ float4 g_c2s[PADN];    // curvature of pc2, at padded sorted pos
__device__ float4 g_moved[MAXN];  // moved curvature, orig order
// i-major partials: ((r*MAXN + i)*2 + c)*KNN + t ; r=0 pc2self(K10), r=1 pc1self(K10), r=2 warp->pc2(K5)
__device__ float  g_pd[3 * MAXN * 2 * KNN];
__device__ int    g_pi[3 * MAXN * 2 * KNN];
__device__ float  g_pmin[MAXN * 2];
__device__ int    g_bins[3 * NB];
__device__ double g_acc[4];  // 0: chamfer fwd, 1: chamfer bwd, 2: smooth, 3: curv

__device__ __forceinline__ int bucketf(float x) {
    int b = (int)((x - XMIN) * BSCALE);
    return min(max(b, 0), NB - 1);
}

__device__ __forceinline__ double warp_red(double v) {
    #pragma unroll
    for (int o = 16; o > 0; o >>= 1)
        v += __shfl_down_sync(0xffffffffu, v, o);
    return v;
}

__global__ void zero_kernel() {
    int gid = blockIdx.x * blockDim.x + threadIdx.x;
    if (gid < 3 * NB) g_bins[gid] = 0;
    if (gid < 4) g_acc[gid] = 0.0;
    if (gid < PAD) {
        float4 lp = make_float4(-1e18f, 0.f, 0.f, 3.4e38f);
        float4 rp = make_float4( 1e18f, 0.f, 0.f, 3.4e38f);
        g_p1s[gid] = lp; g_p1s[PAD + MAXN + gid] = rp;
        g_p2s[gid] = lp; g_p2s[PAD + MAXN + gid] = rp;
        g_ws[gid]  = lp; g_ws[PAD + MAXN + gid]  = rp;
    }
}

__global__ void prep_kernel(const float* __restrict__ pred,
                            const float* __restrict__ gt,
                            const float* __restrict__ coords, int n) {
    int i = blockIdx.x * blockDim.x + threadIdx.x;
    if (i >= n) return;
    float cx = coords[3 * i + 0], cy = coords[3 * i + 1], cz = coords[3 * i + 2];
    float gx = gt[3 * i + 0],     gy = gt[3 * i + 1],     gz = gt[3 * i + 2];
    float fx = pred[3 * i + 0],   fy = pred[3 * i + 1],   fz = pred[3 * i + 2];
    float p2x = cx + gx, p2y = cy + gy, p2z = cz + gz;
    float wx  = cx + fx, wy  = cy + fy, wz  = cz + fz;
    g_pc1[i]  = make_float4(cx, cy, cz, cx * cx + cy * cy + cz * cz);
    g_pc2[i]  = make_float4(p2x, p2y, p2z, p2x * p2x + p2y * p2y + p2z * p2z);
    g_warp[i] = make_float4(wx, wy, wz, wx * wx + wy * wy + wz * wz);
    g_flow[i] = make_float4(fx, fy, fz, 0.f);
    atomicAdd(&g_bins[bucketf(cx)], 1);
    atomicAdd(&g_bins[NB + bucketf(p2x)], 1);
    atomicAdd(&g_bins[2 * NB + bucketf(wx)], 1);
}

// exclusive prefix over each of the 3 histograms; one block of NB threads
__global__ void scan_kernel() {
    __shared__ int s[NB];
    int t = threadIdx.x;
    for (int h = 0; h < 3; h++) {
        int orig = g_bins[h * NB + t];
        s[t] = orig;
        __syncthreads();
        for (int o = 1; o < NB; o <<= 1) {
            int v = (t >= o) ? s[t - o] : 0;
            __syncthreads();
            s[t] += v;
            __syncthreads();
        }
        g_bins[h * NB + t] = s[t] - orig;  // exclusive start
        __syncthreads();
    }
}

// after this kernel g_bins holds bucket END offsets (start+count)
__global__ void scatter_kernel(int n) {
    int i = blockIdx.x * blockDim.x + threadIdx.x;
    if (i >= n) return;
    float4 p1 = g_pc1[i];
    int s1 = atomicAdd(&g_bins[bucketf(p1.x)], 1);
    g_p1s[PAD + s1] = p1;
    g_flow1s[PAD + s1] = g_flow[i];
    g_warp1s[PAD + s1] = g_warp[i];
    g_idx1[s1] = i;
    float4 p2 = g_pc2[i];
    int s2 = atomicAdd(&g_bins[NB + bucketf(p2.x)], 1);
    g_p2s[PAD + s2] = p2;
    float4 w = g_warp[i];
    int sw = atomicAdd(&g_bins[2 * NB + bucketf(w.x)], 1);
    g_ws[PAD + sw] = w;
    g_idxw[sw] = i;
}

template <int K>
__device__ __forceinline__ void insert_sorted(float dm, int j,
                                              float (&d)[K], int (&id)[K],
                                              float& kth) {
    d[K - 1] = dm; id[K - 1] = j;
    #pragma unroll
    for (int s = K - 1; s > 0; --s) {
        if (d[s] < d[s - 1]) {
            float td = d[s]; d[s] = d[s - 1]; d[s - 1] = td;
            int   ti = id[s]; id[s] = id[s - 1]; id[s - 1] = ti;
        }
    }
    kth = d[K - 1];
}

// Windowed outward scan (one side). dm = |p|^2 - 2<q,p>; true = dm + q.w.
// dir=0: tiles [mid-TPB, mid) then leftward; dir=1: [mid, mid+TPB) rightward.
// Block-uniform vote stops the walk when every lane's slack-adjusted x-gap
// to the frontier exceeds kth_true. Pads force the vote at boundaries.
template <int K>
__device__ __forceinline__ void wscan(const float4* __restrict__ C, float4 q,
                                      int mid, int n, int dir, float4* sp,
                                      float (&d)[K], int (&id)[K]) {
    #pragma unroll
    for (int t = 0; t < K; t++) { d[t] = 3.4e38f; id[t] = PAD; }
    float kth = 3.4e38f;
    if (dir == 0) {
        int j = mid - TPB;            // mid >= PAD = TPB, so j >= 0
        while (j >= 0) {
            __syncthreads();
            sp[threadIdx.x] = C[j + threadIdx.x];
            __syncthreads();
            #pragma unroll 8
            for (int t = TPB - 1; t >= 0; --t) {   // near-to-far
                float4 p = sp[t];
                float dot = fmaf(q.x, p.x, fmaf(q.y, p.y, q.z * p.z));
                float dm  = fmaf(-2.f, dot, p.w);
                if (dm < kth) insert_sorted<K>(dm, j + t, d, id, kth);
            }
            j -= TPB;
            if (j < 0) break;
            float fx = C[j + TPB - 1].x;           // frontier (closest of next tile)
            float dxm = q.x - fx - BW;
            bool sat = (dxm > 0.f) && (dxm * dxm > kth + q.w);
            if (__syncthreads_and(sat)) break;
        }
    } else {
        int j = mid;
        const int jend = PAD + n;
        while (j < jend) {
            __syncthreads();
            sp[threadIdx.x] = C[j + threadIdx.x];
            __syncthreads();
            #pragma unroll 8
            for (int t = 0; t < TPB; ++t) {        // near-to-far
                float4 p = sp[t];
                float dot = fmaf(q.x, p.x, fmaf(q.y, p.y, q.z * p.z));
                float dm  = fmaf(-2.f, dot, p.w);
                if (dm < kth) insert_sorted<K>(dm, j + t, d, id, kth);
            }
            j += TPB;
            if (j >= jend) break;
            float fx = C[j].x;
            float dxm = fx - q.x - BW;
            bool sat = (dxm > 0.f) && (dxm * dxm > kth + q.w);
            if (__syncthreads_and(sat)) break;
        }
    }
}

// min-only variant (reverse chamfer)
__device__ __forceinline__ float wmin(const float4* __restrict__ C, float4 q,
                                      int mid, int n, int dir, float4* sp) {
    float m = 3.4e38f;
    if (dir == 0) {
        int j = mid - TPB;
        while (j >= 0) {
            __syncthreads();
            sp[threadIdx.x] = C[j + threadIdx.x];
            __syncthreads();
            #pragma unroll 8
            for (int t = TPB - 1; t >= 0; --t) {
                float4 p = sp[t];
                float dot = fmaf(q.x, p.x, fmaf(q.y, p.y, q.z * p.z));
                m = fminf(m, fmaf(-2.f, dot, p.w));
            }
            j -= TPB;
            if (j < 0) break;
            float fx = C[j + TPB - 1].x;
            float dxm = q.x - fx - BW;
            bool sat = (dxm > 0.f) && (dxm * dxm > m + q.w);
            if (__syncthreads_and(sat)) break;
        }
    } else {
        int j = mid;
        const int jend = PAD + n;
        while (j < jend) {
            __syncthreads();
            sp[threadIdx.x] = C[j + threadIdx.x];
            __syncthreads();
            #pragma unroll 8
            for (int t = 0; t < TPB; ++t) {
                float4 p = sp[t];
                float dot = fmaf(q.x, p.x, fmaf(q.y, p.y, q.z * p.z));
                m = fminf(m, fmaf(-2.f, dot, p.w));
            }
            j += TPB;
            if (j >= jend) break;
            float fx = C[j].x;
            float dxm = fx - q.x - BW;
            bool sat = (dxm > 0.f) && (dxm * dxm > m + q.w);
            if (__syncthreads_and(sat)) break;
        }
    }
    return m;
}

// grid = (n/TPB, 2, 4): y = side (0 left, 1 right), z = slice.
//  z=0: pc2 self-knn (K10) -> r=0    z=1: pc1 self-knn (K10) -> r=1
//  z=2: warp->pc2 (K5)     -> r=2    z=3: pc2->warp min -> g_pmin
__global__ void __launch_bounds__(TPB) pairs_kernel(int n, const int* __restrict__ kptr) {
    __shared__ float4 sp[TPB];
    const int slice = blockIdx.z;
    const int dir = blockIdx.y;
    const int qbase = blockIdx.x * TPB;
    const int i = qbase + threadIdx.x;   // sorted query index (n % TPB == 0)

    const float4* __restrict__ Q;
    const float4* __restrict__ C;
    int hc;
    if      (slice == 0) { Q = g_p2s; C = g_p2s; hc = 1; }
    else if (slice == 1) { Q = g_p1s; C = g_p1s; hc = 0; }
    else if (slice == 2) { Q = g_ws;  C = g_p2s; hc = 1; }
    else                 { Q = g_p2s; C = g_ws;  hc = 2; }

    float4 q = Q[PAD + i];
    float xmed = Q[PAD + qbase + TPB / 2].x;          // block-uniform
    int mid = PAD + g_bins[hc * NB + bucketf(xmed)];  // bucket end = split point

    if (slice == 0 || slice == 1) {
        float d[KNN]; int id[KNN];
        wscan<KNN>(C, q, mid, n, dir, sp, d, id);
        int b = ((slice * MAXN + i) * 2 + dir) * KNN;
        #pragma unroll
        for (int t = 0; t < KNN; t++) { g_pd[b + t] = d[t] + q.w; g_pi[b + t] = id[t]; }
    } else if (slice == 2) {
        float d[KNN5]; int id[KNN5];
        wscan<KNN5>(C, q, mid, n, dir, sp, d, id);
        int b = ((2 * MAXN + i) * 2 + dir) * KNN;
        #pragma unroll
        for (int t = 0; t < KNN5; t++) { g_pd[b + t] = d[t] + q.w; g_pi[b + t] = id[t]; }
    } else {
        float m = wmin(C, q, mid, n, dir, sp);
        g_pmin[i * 2 + dir] = m + q.w;
    }
}

// Stable 2-chunk merge (true distances, strict '<'). Ids are padded sorted
// positions. Ties between distinct candidates are measure-zero for this data.
template <int K>
__device__ __forceinline__ void merge_topk(int r, int i, float (&d)[K], int (&id)[K]) {
    #pragma unroll
    for (int t = 0; t < K; t++) { d[t] = 3.4e38f; id[t] = PAD; }
    int base = (r * MAXN + i) * 2 * KNN;
    #pragma unroll
    for (int c = 0; c < 2; c++) {
        #pragma unroll
        for (int t = 0; t < K; t++) {
            float dist = g_pd[base + c * KNN + t];
            int j = g_pi[base + c * KNN + t];
            if (dist < d[K - 1]) {
                d[K - 1] = dist; id[K - 1] = j;
                #pragma unroll
                for (int s = K - 1; s > 0; --s) {
                    if (d[s] < d[s - 1]) {
                        float td = d[s]; d[s] = d[s - 1]; d[s - 1] = td;
                        int   ti = id[s]; id[s] = id[s - 1]; id[s - 1] = ti;
                    }
                }
            }
        }
    }
}

// grid.y: 0 = c2 curvature, 1 = moved curvature + smoothness, 2 = reverse chamfer
__global__ void consumeA_kernel(int n, const int* __restrict__ kptr) {
    int i = blockIdx.x * blockDim.x + threadIdx.x;
    int task = blockIdx.y;
    if (task == 0) {
        if (i >= n) return;
        float d[KNN]; int id[KNN];
        merge_topk<KNN>(0, i, d, id);
        float4 qq = g_p2s[PAD + i];
        float sx = 0.f, sy = 0.f, sz = 0.f;
        #pragma unroll
        for (int t = 0; t < KNN; t++) {
            float4 p = g_p2s[id[t]];
            sx += p.x; sy += p.y; sz += p.z;
        }
        g_c2s[PAD + i] = make_float4((sx - 10.f * qq.x) / 9.f,
                                     (sy - 10.f * qq.y) / 9.f,
                                     (sz - 10.f * qq.z) / 9.f, 0.f);
    } else if (task == 1) {
        double sm_d = 0.0;
        if (i < n) {
            float d[KNN]; int id[KNN];
            merge_topk<KNN>(1, i, d, id);
            float4 w = g_warp1s[PAD + i];
            float sx = 0.f, sy = 0.f, sz = 0.f;
            #pragma unroll
            for (int t = 0; t < KNN; t++) {
                float4 p = g_warp1s[id[t]];
                sx += p.x; sy += p.y; sz += p.z;
            }
            g_moved[g_idx1[i]] = make_float4((sx - 10.f * w.x) / 9.f,
                                             (sy - 10.f * w.y) / 9.f,
                                             (sz - 10.f * w.z) / 9.f, 0.f);
            int k = *kptr;
            float4 f = g_flow1s[PAD + i];
            float sm = 0.f;
            #pragma unroll
            for (int t = 0; t < KNN; t++) {
                if (t < k) {
                    float4 gfl = g_flow1s[id[t]];
                    float dx = gfl.x - f.x, dy = gfl.y - f.y, dz = gfl.z - f.z;
                    float sq = dx * dx + dy * dy + dz * dz;
                    sm += sqrtf(sq);   // sq==0 (self) -> 0, matches safe-norm
                }
            }
            sm_d = (double)(sm / 8.f);
        }
        double v = warp_red(sm_d);
        if ((threadIdx.x & 31) == 0) atomicAdd(&g_acc[2], v);
    } else {
        double v = 0.0;
        if (i < n) {
            float m = fminf(g_pmin[i * 2], g_pmin[i * 2 + 1]);
            v = (double)m;
        }
        double s = warp_red(v);
        if ((threadIdx.x & 31) == 0) atomicAdd(&g_acc[1], s);
    }
}

// warp->pc2 top-5 merge -> chamfer fwd + interpolated-curvature loss
__global__ void cross_consume_kernel(int n) {
    int i = blockIdx.x * blockDim.x + threadIdx.x;
    double d1 = 0.0, cv = 0.0;
    if (i < n) {
        float d[KNN5]; int id[KNN5];
        merge_topk<KNN5>(2, i, d, id);
        d1 = (double)d[0];
        float w[KNN5]; float wsum = 0.f;
        #pragma unroll
        for (int t = 0; t < KNN5; t++) { w[t] = 1.f / (d[t] + 1e-8f); wsum += w[t]; }
        float ix = 0.f, iy = 0.f, iz = 0.f;
        #pragma unroll
        for (int t = 0; t < KNN5; t++) {
            float wn = w[t] / wsum;
            float4 c = g_c2s[id[t]];
            ix = fmaf(wn, c.x, ix);
            iy = fmaf(wn, c.y, iy);
            iz = fmaf(wn, c.z, iz);
        }
        float4 m = g_moved[g_idxw[i]];
        float ex = ix - m.x, ey = iy - m.y, ez = iz - m.z;
        cv = (double)(ex * ex + ey * ey + ez * ez);
    }
    double v0 = warp_red(d1);
    double v1 = warp_red(cv);
    if ((threadIdx.x & 31) == 0) {
        atomicAdd(&g_acc[0], v0);
        atomicAdd(&g_acc[3], v1);
    }
}

__global__ void finalize_kernel(float* __restrict__ out) {
    if (threadIdx.x == 0) {
        double chamfer = g_acc[0] + g_acc[1];
        double total = 0.02 * chamfer      // F_CHAMFER * ALPHA0
                     + 0.006 * g_acc[3]    // F_CURVATURE * ALPHA0
                     + 0.01  * g_acc[2];   // F_SMOOTH * ALPHA0
        out[0] = (float)total;
    }
}

extern "C" void kernel_launch(void* const* d_in, const int* in_sizes, int n_in,
                              void* d_out, int out_size) {
    const float* pred   = (const float*)d_in[0];  // registration_pred (1,N,3)
    const float* gt     = (const float*)d_in[1];  // registration_gt   (1,N,3)
    const float* coords = (const float*)d_in[2];  // coords            (N,3)
    const int*   kptr   = (const int*)d_in[3];    // smoothness_k

    int n = in_sizes[2] / 3;   // 8192
    int cb = (n + 255) / 256;

    zero_kernel<<<3, 1024>>>();
    prep_kernel<<<cb, 256>>>(pred, gt, coords, n);
    scan_kernel<<<1, NB>>>();
    scatter_kernel<<<cb, 256>>>(n);
    pairs_kernel<<<dim3(n / TPB, 2, 4), TPB>>>(n, kptr);
    consumeA_kernel<<<dim3(cb, 3), 256>>>(n, kptr);
    cross_consume_kernel<<<cb, 256>>>(n);
    finalize_kernel<<<1, 32>>>((float*)d_out);
}